// round 15
// baseline (speedup 1.0000x reference)
#include <cuda_runtime.h>
#include <cstdint>

#define BSZ  8
#define CDIM 64
#define NPTS 4096
#define KNN  20
#define OC   64
#define QT   128         // queries per block in k_knn

// ---------------- scratch (device globals; no allocation) ----------------
__device__ float g_sq [BSZ*NPTS];     // NEGATED squared norms: -|x|^2
__device__ float g_u  [BSZ*NPTS*OC];
__device__ float g_v  [BSZ*NPTS*OC];
__device__ int   g_idx[BSZ*NPTS*KNN];
__device__ float g_mxv[BSZ*NPTS*OC];
__device__ float g_mnv[BSZ*NPTS*OC];
__device__ float g_S1[OC];
__device__ float g_S2[OC];
__device__ float g_ga[OC];
__device__ float g_gb[OC];

// packed fp32x2 helpers (FFMA2 only reachable via PTX)
#define FMA2(acc, a, b) \
    asm("fma.rn.f32x2 %0, %1, %2, %0;" : "+l"(acc) : "l"(a), "l"(b))
#define UNPK2(lo, hi, src) \
    asm("mov.b64 {%0, %1}, %2;" : "=f"(lo), "=f"(hi) : "l"(src))

// ---------------- kernel 0: NEGATED squared norms ----------------
__global__ __launch_bounds__(256) void k_sq(const float* __restrict__ x) {
    const int b = blockIdx.y;
    const int n = blockIdx.x * 256 + threadIdx.x;
    const float* xb = x + (size_t)b * CDIM * NPTS;
    float s = 0.f;
#pragma unroll 8
    for (int c = 0; c < CDIM; ++c) {
        float t = xb[c * NPTS + n];
        s += t * t;
    }
    g_sq[b * NPTS + n] = -s;
}

// ---------------- kernel Z: zero stats (pads launch order so ncu's
// fixed capture slot lands on k_knn) ----------------
__global__ void k_zstat() {
    if (threadIdx.x < OC) {
        g_S1[threadIdx.x] = 0.f;
        g_S2[threadIdx.x] = 0.f;
    }
}

// ---------------- kernel A: u = W1*x, v = (W2-W1)*x, layout [b][n][o] ---
__global__ __launch_bounds__(256) void k_uv(const float* __restrict__ x,
                                            const float* __restrict__ W) {
    __shared__ float Wc[128 * 64];
    __shared__ float xt[64 * 32];
    const int b = blockIdx.y, n0 = blockIdx.x * 32;
    const int tx = threadIdx.x, ty = threadIdx.y, tid = ty * 16 + tx;

    for (int i = tid; i < 128 * 64; i += 256) {
        int r = i >> 6, c = i & 63;
        float wv;
        if (r < 64) wv = W[r * 128 + c];
        else        wv = W[(r - 64) * 128 + 64 + c] - W[(r - 64) * 128 + c];
        Wc[i] = wv;
    }
    const float* xb = x + (size_t)b * CDIM * NPTS;
    for (int i = tid; i < 64 * 32; i += 256) {
        int c = i >> 5, nn = i & 31;
        xt[i] = xb[c * NPTS + n0 + nn];
    }
    __syncthreads();

    float acc[8][2] = {};
#pragma unroll 8
    for (int c = 0; c < 64; ++c) {
        float2 bv = *(const float2*)&xt[c * 32 + tx * 2];
#pragma unroll
        for (int i = 0; i < 8; ++i) {
            float a = Wc[(ty * 8 + i) * 64 + c];
            acc[i][0] += a * bv.x;
            acc[i][1] += a * bv.y;
        }
    }
    __syncthreads();

    if (ty < 8) {
#pragma unroll
        for (int i = 0; i < 8; ++i) {
            Wc[(tx * 2 + 0) * 65 + ty * 8 + i] = acc[i][0];
            Wc[(tx * 2 + 1) * 65 + ty * 8 + i] = acc[i][1];
        }
    }
    __syncthreads();
    {
        float* dst = g_u + ((size_t)b * NPTS + n0) * OC;
        for (int i = tid; i < 32 * 64; i += 256) {
            int nn = i >> 6, oo = i & 63;
            dst[i] = Wc[nn * 65 + oo];
        }
    }
    __syncthreads();
    if (ty >= 8) {
#pragma unroll
        for (int i = 0; i < 8; ++i) {
            Wc[(tx * 2 + 0) * 65 + (ty - 8) * 8 + i] = acc[i][0];
            Wc[(tx * 2 + 1) * 65 + (ty - 8) * 8 + i] = acc[i][1];
        }
    }
    __syncthreads();
    {
        float* dst = g_v + ((size_t)b * NPTS + n0) * OC;
        for (int i = tid; i < 32 * 64; i += 256) {
            int nn = i >> 6, oo = i & 63;
            dst[i] = Wc[nn * 65 + oo];
        }
    }
}

// ---------------- kernel B: FFMA2 Gram, pre-duplicated B ----------------
// 512 threads = 16 warps. tx = tid&15 -> cols {tx, tx+16, tx+32, tx+48};
// ty = tid>>4 -> rows 4ty..4ty+3. Warp w = 2 ty values -> rows 8w..8w+7
// (keys rows are warp-private). B is duplicated in smem once per tile:
// Bd[c][2j]=Bd[c][2j+1]=b_j, so the inner loop has NO DUP2 MOVs:
//   per c-step: 1x ld.v2.u64 (A, warp-broadcast) + 4x ld.u64 (B, banks 2tx
//   conflict-free + half-warp broadcast) + 8 FFMA2  = 13 issues / 16 MACs.
//
// smem (floats): qs[64c][128q] | Bd[64c][128] | keys[128][66] | nsq[64]
#define KPAD  66
#define SM_QS   0
#define SM_BD   (64 * QT)
#define SM_KEYS (SM_BD + 64 * 128)
#define SM_NSQ  (SM_KEYS + QT * KPAD)
#define SM_FLOATS (SM_NSQ + 64)
#define SM_BYTES  (SM_FLOATS * 4)

__device__ __forceinline__ void insert_cand(float k, int m, float& tk, int& ti,
                                            float& thr, int& minl, int lane) {
    unsigned bal = __ballot_sync(0xffffffffu, k > thr);
    while (bal) {
        int src = __ffs(bal) - 1;
        bal &= bal - 1;
        float ck = __shfl_sync(0xffffffffu, k, src);
        int   cm = __shfl_sync(0xffffffffu, m, src);
        if (ck > thr) {                  // re-check: thr may have risen
            if (lane == minl) { tk = ck; ti = cm; }
            float mv = (lane < KNN) ? tk : 3.4e38f;
            int   ml = lane;
#pragma unroll
            for (int off = 16; off; off >>= 1) {
                float ov = __shfl_xor_sync(0xffffffffu, mv, off);
                int   ol = __shfl_xor_sync(0xffffffffu, ml, off);
                if (ov < mv || (ov == mv && ol < ml)) { mv = ov; ml = ol; }
            }
            thr = mv; minl = ml;         // uniform across warp
        }
    }
}

extern __shared__ float sm[];

__global__ __launch_bounds__(512, 2) void k_knn(const float* __restrict__ x) {
    float* qs   = sm + SM_QS;
    float* Bd   = sm + SM_BD;
    float* keys = sm + SM_KEYS;
    float* nsq  = sm + SM_NSQ;

    const int b  = blockIdx.y;
    const int q0 = blockIdx.x * QT;
    const int tid  = threadIdx.x;
    const int tx   = tid & 15;          // cols {tx, tx+16, tx+32, tx+48}
    const int ty   = tid >> 4;          // rows 4ty..4ty+3
    const int lane = tid & 31, warp = tid >> 5;   // 16 warps, 8 rows each
    const float* xb = x + (size_t)b * CDIM * NPTS;

    // load query tile [c][q]
    for (int i = tid; i < 64 * QT; i += 512) {
        int c = i >> 7, qq = i & 127;
        qs[i] = xb[c * NPTS + q0 + qq];
    }

    float tk[8], thr[8];
    int   ti[8], minl[8];
#pragma unroll
    for (int r = 0; r < 8; ++r) {
        tk[r] = -3.4e38f; ti[r] = 0; thr[r] = -3.4e38f; minl[r] = 0;
    }

    for (int t = 0; t < NPTS / 64; ++t) {
        const int m0 = t * 64;
        __syncthreads();   // [1] Bd(t-1)/nsq consumed; keys(t-1) written

        // ---- load + DUPLICATE this tile's B into smem; load negsq ----
#pragma unroll
        for (int s = 0; s < 8; ++s) {
            int i = tid + s * 512;          // 4096 elements
            int c = i >> 6, col = i & 63;
            float v = xb[c * NPTS + m0 + col];
            float2 d; d.x = v; d.y = v;
            *(float2*)&Bd[c * 128 + 2 * col] = d;
        }
        if (tid < 64) nsq[tid] = g_sq[b * NPTS + m0 + tid];

        // ---- selection for PREVIOUS tile (warp-private keys rows) ----
        if (t > 0) {
            const int mp = m0 - 64;
#pragma unroll
            for (int r = 0; r < 8; ++r) {
                const float* krow = &keys[(warp * 8 + r) * KPAD];
                float k0 = krow[lane];
                float k1 = krow[32 + lane];
                insert_cand(k0, mp + lane,      tk[r], ti[r], thr[r], minl[r], lane);
                insert_cand(k1, mp + 32 + lane, tk[r], ti[r], thr[r], minl[r], lane);
            }
        }
        __syncthreads();   // [2] Bd/nsq visible; keys(t-1) consumed

        // ---- MOV-free FFMA2 loop: 4 rows x 4 strided cols ----
        unsigned long long acc[2][4];
#pragma unroll
        for (int i = 0; i < 2; ++i)
#pragma unroll
            for (int j = 0; j < 4; ++j) acc[i][j] = 0ull;

#pragma unroll 8
        for (int c = 0; c < 64; ++c) {
            ulonglong2 A = *(const ulonglong2*)&qs[c * QT + ty * 4];
            const float* bdc = &Bd[c * 128 + 2 * tx];
            unsigned long long b0 = *(const unsigned long long*)&bdc[0];
            unsigned long long b1 = *(const unsigned long long*)&bdc[32];
            unsigned long long b2 = *(const unsigned long long*)&bdc[64];
            unsigned long long b3 = *(const unsigned long long*)&bdc[96];
            FMA2(acc[0][0], A.x, b0); FMA2(acc[0][1], A.x, b1);
            FMA2(acc[0][2], A.x, b2); FMA2(acc[0][3], A.x, b3);
            FMA2(acc[1][0], A.y, b0); FMA2(acc[1][1], A.y, b1);
            FMA2(acc[1][2], A.y, b2); FMA2(acc[1][3], A.y, b3);
        }

        // ---- epilogue: keys = 2*dot + negsq -> keys smem ----
        {
            float n0 = nsq[tx], n1 = nsq[tx + 16];
            float n2 = nsq[tx + 32], n3 = nsq[tx + 48];
#pragma unroll
            for (int i = 0; i < 2; ++i) {
                float lo, hi;
                float* kr0 = &keys[(ty * 4 + 2 * i) * KPAD];
                float* kr1 = kr0 + KPAD;
                UNPK2(lo, hi, acc[i][0]);
                kr0[tx]      = fmaf(2.f, lo, n0); kr1[tx]      = fmaf(2.f, hi, n0);
                UNPK2(lo, hi, acc[i][1]);
                kr0[tx + 16] = fmaf(2.f, lo, n1); kr1[tx + 16] = fmaf(2.f, hi, n1);
                UNPK2(lo, hi, acc[i][2]);
                kr0[tx + 32] = fmaf(2.f, lo, n2); kr1[tx + 32] = fmaf(2.f, hi, n2);
                UNPK2(lo, hi, acc[i][3]);
                kr0[tx + 48] = fmaf(2.f, lo, n3); kr1[tx + 48] = fmaf(2.f, hi, n3);
            }
        }
        __syncwarp();     // keys rows visible to sibling lanes
    }

    // final tile's selection
    __syncthreads();
    {
        const int mp = NPTS - 64;
#pragma unroll
        for (int r = 0; r < 8; ++r) {
            const float* krow = &keys[(warp * 8 + r) * KPAD];
            float k0 = krow[lane];
            float k1 = krow[32 + lane];
            insert_cand(k0, mp + lane,      tk[r], ti[r], thr[r], minl[r], lane);
            insert_cand(k1, mp + 32 + lane, tk[r], ti[r], thr[r], minl[r], lane);
        }
    }

    if (lane < KNN) {
#pragma unroll
        for (int r = 0; r < 8; ++r)
            g_idx[((size_t)b * NPTS + q0 + warp * 8 + r) * KNN + lane] = ti[r];
    }
}

// ---------------- kernel C: one gather pass: max/min + BN stats ----------
__global__ __launch_bounds__(256) void k_gather() {
    __shared__ int   sidx[4][KNN];
    __shared__ float red[2][4][64];
    const int o = threadIdx.x;
    const int py = threadIdx.y;
    const int tid = py * 64 + o;
    const int b = blockIdx.y;
    const int n0 = blockIdx.x * 64;
    const float* ub = g_u + (size_t)b * NPTS * OC;
    float s1 = 0.f, s2 = 0.f;

    for (int it = 0; it < 16; ++it) {
        __syncthreads();
        if (tid < 4 * KNN) {
            int g = tid / KNN, j = tid % KNN;
            sidx[g][j] = g_idx[((size_t)b * NPTS + n0 + it * 4 + g) * KNN + j];
        }
        __syncthreads();
        const int n = n0 + it * 4 + py;
        float s = 0.f, q = 0.f, mx = -3.4e38f, mn = 3.4e38f;
#pragma unroll
        for (int j = 0; j < KNN; ++j) {
            float val = ub[(size_t)sidx[py][j] * OC + o];
            s += val; q += val * val;
            mx = fmaxf(mx, val); mn = fminf(mn, val);
        }
        const size_t off = ((size_t)b * NPTS + n) * OC + o;
        float vv = g_v[off];
        g_mxv[off] = mx + vv;
        g_mnv[off] = mn + vv;
        s1 += (float)KNN * vv + s;
        s2 += (float)KNN * vv * vv + 2.f * vv * s + q;
    }
    red[0][py][o] = s1;
    red[1][py][o] = s2;
    __syncthreads();
    if (py == 0) {
        float a = red[0][0][o] + red[0][1][o] + red[0][2][o] + red[0][3][o];
        float c = red[1][0][o] + red[1][1][o] + red[1][2][o] + red[1][3][o];
        atomicAdd(&g_S1[o], a);
        atomicAdd(&g_S2[o], c);
    }
}

// ---------------- kernel D: finalize BN affine coefficients --------------
__global__ void k_finalize(const float* __restrict__ gamma,
                           const float* __restrict__ beta) {
    int o = threadIdx.x;
    const float M = (float)BSZ * (float)NPTS * (float)KNN;
    float mean = g_S1[o] / M;
    float var  = g_S2[o] / M - mean * mean;
    float a = gamma[o] * rsqrtf(var + 1e-5f);
    g_ga[o] = a;
    g_gb[o] = beta[o] - mean * a;
}

// ---------------- kernel E: affine + LeakyReLU + transpose to [b][o][n] --
__global__ __launch_bounds__(256) void k_out(float* __restrict__ out) {
    __shared__ float tile[64][65];
    const int o = threadIdx.x, ty = threadIdx.y;
    const int b = blockIdx.y, n0 = blockIdx.x * 64;
    const float a = g_ga[o], bc = g_gb[o];
#pragma unroll
    for (int it = 0; it < 16; ++it) {
        int nl = it * 4 + ty;
        size_t off = ((size_t)b * NPTS + n0 + nl) * OC + o;
        float raw = (a >= 0.f) ? g_mxv[off] : g_mnv[off];
        float val = fmaf(a, raw, bc);
        tile[nl][o] = (val >= 0.f) ? val : 0.2f * val;
    }
    __syncthreads();
#pragma unroll
    for (int it = 0; it < 16; ++it) {
        int oo = it * 4 + ty;
        out[((size_t)b * OC + oo) * NPTS + n0 + o] = tile[o][oo];
    }
}

// ---------------- launch ----------------
extern "C" void kernel_launch(void* const* d_in, const int* in_sizes, int n_in,
                              void* d_out, int out_size) {
    const float* x     = (const float*)d_in[0];
    const float* W     = (const float*)d_in[1];
    const float* gamma = (const float*)d_in[2];
    const float* beta  = (const float*)d_in[3];
    float* out = (float*)d_out;

    cudaFuncSetAttribute(k_knn, cudaFuncAttributeMaxDynamicSharedMemorySize,
                         SM_BYTES);

    k_sq      <<<dim3(NPTS / 256, BSZ), 256>>>(x);
    k_uv      <<<dim3(NPTS / 32,  BSZ), dim3(16, 16)>>>(x, W);
    k_zstat   <<<1, 64>>>();                        // pads slot 3 -> k_knn profiled
    k_knn     <<<dim3(NPTS / QT,  BSZ), 512, SM_BYTES>>>(x);
    k_gather  <<<dim3(NPTS / 64,  BSZ), dim3(64, 4)>>>();
    k_finalize<<<1, 64>>>(gamma, beta);
    k_out     <<<dim3(NPTS / 64,  BSZ), dim3(64, 4)>>>(out);
}